// round 14
// baseline (speedup 1.0000x reference)
#include <cuda_runtime.h>
#include <cuda_bf16.h>
#include <cstdint>
#include <cstddef>

#define BB   16
#define NPTS 10000
#define HID  128
#define OUTD 5
#define THR  256
#define PTS  128
#define NBLK 79             // ceil(10000/128)

// scalar region (float indices into sm[])
#define SX_F    0           // 128*4
#define SGATE_F 512         // 4*128
#define SBC_F   1024        // 5*128
#define SBIAS_F 1664        // bt (3*128) + btf (128)
#define SAT_F   2176
#define SWQ_F   2688
#define SW0_F   3200
#define SB0_F   3712        // 128 -> scalar region ends at 3840 floats = 15360 B
// byte regions
#define AHI_BYTE 15360      // A hi tile: 128 rows * 272B = 34816
#define ALO_BYTE 50176      // A lo tile
#define ABYTES   34816
#define ASTRIDE  272        // 136 bf16 per row
#define SMEM_BYTES 84992

typedef unsigned long long u64;

__device__ float g_gate[BB * 4 * HID];
__device__ float g_bc[BB * OUTD * HID];
__device__ __align__(16) uint4 g_Wfrag[4][4096];   // [layer][(ks*16+n0)*32+lane]

__device__ __forceinline__ float tanh_ap(float x) {
    float r; asm("tanh.approx.f32 %0, %1;" : "=f"(r) : "f"(x)); return r;
}
__device__ __forceinline__ float sin_ap(float x) {
    float r; asm("sin.approx.f32 %0, %1;" : "=f"(r) : "f"(x)); return r;
}
__device__ __forceinline__ uint32_t smem_u32(const void* p) {
    uint32_t a;
    asm("{ .reg .u64 t; cvta.to.shared.u64 t, %1; cvt.u32.u64 %0, t; }" : "=r"(a) : "l"(p));
    return a;
}
__device__ __forceinline__ uint32_t pkbf(float e0, float e1) {
    uint32_t r; asm("cvt.rn.satfinite.bf16x2.f32 %0, %1, %2;" : "=r"(r) : "f"(e1), "f"(e0));
    return r;
}
__device__ __forceinline__ void split2(float v, float& hf, float& lf) {
    __nv_bfloat16 h = __float2bfloat16_rn(v);
    hf = __bfloat162float(h);
    lf = v - hf;
}
__device__ __forceinline__ void ldmat4(uint32_t* r, uint32_t addr) {
    asm volatile("ldmatrix.sync.aligned.m8n8.x4.shared.b16 {%0,%1,%2,%3}, [%4];"
                 : "=r"(r[0]), "=r"(r[1]), "=r"(r[2]), "=r"(r[3]) : "r"(addr));
}
__device__ __forceinline__ void hmma(float (&d)[4], const uint32_t* a, uint32_t b0, uint32_t b1) {
    asm volatile(
        "mma.sync.aligned.m16n8k16.row.col.f32.bf16.bf16.f32 "
        "{%0,%1,%2,%3}, {%4,%5,%6,%7}, {%8,%9}, {%0,%1,%2,%3};"
        : "+f"(d[0]), "+f"(d[1]), "+f"(d[2]), "+f"(d[3])
        : "r"(a[0]), "r"(a[1]), "r"(a[2]), "r"(a[3]), "r"(b0), "r"(b1));
}
__device__ __forceinline__ void fma2(u64& d, u64 a, u64 b) {
    asm("fma.rn.f32x2 %0, %1, %2, %0;" : "+l"(d) : "l"(a), "l"(b));
}
__device__ __forceinline__ float2 up2(u64 v) {
    float2 r; asm("mov.b64 {%0, %1}, %2;" : "=f"(r.x), "=f"(r.y) : "l"(v)); return r;
}
__device__ __forceinline__ void bar64(int id) {
    asm volatile("bar.sync %0, 64;" :: "r"(id) : "memory");
}

// ---------------------------------------------------------------------------
// Fused prep: blocks 0..31 pack W fragments; blocks 32..47 branch MLP.
// ---------------------------------------------------------------------------
__global__ void prep_kernel(const float* __restrict__ Wt,  const float* __restrict__ Wtf,
                            const float* __restrict__ params,
                            const float* __restrict__ Wb0, const float* __restrict__ bb0,
                            const float* __restrict__ Wb,  const float* __restrict__ bbv,
                            const float* __restrict__ Wbf, const float* __restrict__ bbf,
                            const float* __restrict__ ab,  const float* __restrict__ wb)
{
    if (blockIdx.x < 32) {
        const int l = blockIdx.x >> 3, chunk = blockIdx.x & 7;
        const float* W = (l < 3) ? (Wt + (size_t)l * HID * HID) : Wtf;
        const int e0 = chunk * 512;
        for (int e = e0 + threadIdx.x; e < e0 + 512; e += 256) {
            int ks = e >> 9, n0 = (e >> 5) & 15, t = e & 31;
            int n  = n0 * 8 + (t >> 2);
            int kb = ks * 16 + (t & 3) * 2;
            float w00 = W[(size_t)kb * HID + n],       w01 = W[(size_t)(kb + 1) * HID + n];
            float w10 = W[(size_t)(kb + 8) * HID + n], w11 = W[(size_t)(kb + 9) * HID + n];
            float h00, l00, h01, l01, h10, l10, h11, l11;
            split2(w00, h00, l00); split2(w01, h01, l01);
            split2(w10, h10, l10); split2(w11, h11, l11);
            uint4 u;
            u.x = pkbf(h00, h01); u.y = pkbf(h10, h11);
            u.z = pkbf(l00, l01); u.w = pkbf(l10, l11);
            g_Wfrag[l][e] = u;
        }
        return;
    }

    // ---- branch MLP ----
    __shared__ float h_s[HID];
    __shared__ float part[HID];
    const int b = blockIdx.x - 32, tid = threadIdx.x;
    const int j = tid & 127, hh = tid >> 7;

    float g = 0.f;
    if (hh == 0) {
        float z = bb0[j];
#pragma unroll
        for (int c = 0; c < 6; ++c) z = fmaf(params[b * 6 + c], Wb0[c * HID + j], z);
        float v = tanh_ap(z) + ab[j] * sin_ap(wb[j] * z);
        g = v; g_gate[(b * 4) * HID + j] = g; h_s[j] = v;
    }
    __syncthreads();

    for (int i = 0; i < 3; ++i) {
        const float* W = Wb + (size_t)i * HID * HID;
        float zz = (hh == 0) ? bbv[i * HID + j] : 0.f;
        const int k0 = hh * 64;
#pragma unroll 4
        for (int k = 0; k < 64; ++k) zz = fmaf(h_s[k0 + k], W[(size_t)(k0 + k) * HID + j], zz);
        if (hh) part[j] = zz;
        __syncthreads();
        float v = 0.f;
        if (hh == 0) {
            float z = zz + part[j];
            v = tanh_ap(z) + ab[(i + 1) * HID + j] * sin_ap(wb[(i + 1) * HID + j] * z);
            g += v; g_gate[(b * 4 + i + 1) * HID + j] = g;
        }
        __syncthreads();
        if (hh == 0) h_s[j] = v;
        __syncthreads();
    }

#pragma unroll
    for (int o = 0; o < OUTD; ++o) {
        float zz = (hh == 0) ? bbf[o * HID + j] : 0.f;
        const int k0 = hh * 64;
#pragma unroll 4
        for (int k = 0; k < 64; ++k)
            zz = fmaf(h_s[k0 + k], Wbf[(size_t)(k0 + k) * (HID * OUTD) + o * HID + j], zz);
        if (hh) part[j] = zz;
        __syncthreads();
        if (hh == 0) g_bc[(b * OUTD + o) * HID + j] = zz + part[j];
        __syncthreads();
    }
}

// ---------------------------------------------------------------------------
// Trunk: 128 pts/block, 8 warps, 2 blocks/SM. Warp pair (s, s+4) owns rows
// 32s..32s+31: warp s cols 0..63, warp s+4 cols 64..127. A-fragment
// double-buffering hides LDS latency under the HMMA stream.
// ---------------------------------------------------------------------------
__global__ void __launch_bounds__(THR, 2)
trunk_kernel(const float* __restrict__ coords, const float* __restrict__ sdf,
             const float* __restrict__ Wt0, const float* __restrict__ bt0,
             const float* __restrict__ btv, const float* __restrict__ btf,
             const float* __restrict__ at,  const float* __restrict__ wt,
             float* __restrict__ out)
{
    extern __shared__ float sm[];
    char* smc = (char*)sm;
    const uint32_t sbase = smem_u32(sm);

    const int b    = blockIdx.y;
    const int p0   = blockIdx.x * PTS;
    const int tid  = threadIdx.x;
    const int warp = tid >> 5;
    const int lane = tid & 31;
    const int w4   = warp & 3;          // row-strip id (32 rows)
    const int nh   = warp >> 2;         // n-half

    // stage inputs + scalars
    if (tid < PTS) {
        int p = p0 + tid;
        float4 v = make_float4(0.f, 0.f, 0.f, 0.f);
        if (p < NPTS) {
            const float* c = coords + ((size_t)b * NPTS + p) * 3;
            v.x = c[0]; v.y = c[1]; v.z = c[2];
            v.w = sdf[(size_t)b * NPTS + p];
        }
        ((float4*)&sm[SX_F])[tid] = v;
    }
    for (int i = tid; i < 512; i += THR) sm[SGATE_F + i] = g_gate[b * 512 + i];
    for (int i = tid; i < 640; i += THR) sm[SBC_F + i]   = g_bc[b * 640 + i];
    for (int i = tid; i < 384; i += THR) sm[SBIAS_F + i] = btv[i];
    for (int i = tid; i < 128; i += THR) sm[SBIAS_F + 384 + i] = btf[i];
    for (int i = tid; i < 512; i += THR) sm[SAT_F + i] = at[i];
    for (int i = tid; i < 512; i += THR) sm[SWQ_F + i] = wt[i];
    for (int i = tid; i < 512; i += THR) sm[SW0_F + i] = Wt0[i];
    for (int i = tid; i < 128; i += THR) sm[SB0_F + i] = bt0[i];
    __syncthreads();

    char* AhiC = smc + AHI_BYTE;
    char* AloC = smc + ALO_BYTE;

    // ---- layer 0: thread handles point r=tid/2, column half ch=tid&1 ----
    {
        const int r = tid >> 1, ch = tid & 1;
        float4 xv = ((float4*)&sm[SX_F])[r];
#pragma unroll 1
        for (int j0 = ch * 64; j0 < ch * 64 + 64; j0 += 8) {
            float hf[8], lf[8];
#pragma unroll
            for (int jj = 0; jj < 8; ++jj) {
                int j = j0 + jj;
                float z = fmaf(xv.x, sm[SW0_F + j],
                          fmaf(xv.y, sm[SW0_F + 128 + j],
                          fmaf(xv.z, sm[SW0_F + 256 + j],
                          fmaf(xv.w, sm[SW0_F + 384 + j], sm[SB0_F + j]))));
                float v = (tanh_ap(z) + sm[SAT_F + j] * sin_ap(sm[SWQ_F + j] * z)) * sm[SGATE_F + j];
                split2(v, hf[jj], lf[jj]);
            }
            uint4 hq, lq;
            hq.x = pkbf(hf[0], hf[1]); hq.y = pkbf(hf[2], hf[3]);
            hq.z = pkbf(hf[4], hf[5]); hq.w = pkbf(hf[6], hf[7]);
            lq.x = pkbf(lf[0], lf[1]); lq.y = pkbf(lf[2], lf[3]);
            lq.z = pkbf(lf[4], lf[5]); lq.w = pkbf(lf[6], lf[7]);
            *(uint4*)(AhiC + r * ASTRIDE + j0 * 2) = hq;
            *(uint4*)(AloC + r * ASTRIDE + j0 * 2) = lq;
        }
    }
    __syncthreads();                     // layer-0 writes visible to all pairs

    const int r0 = w4 * 32;
    const int qm = lane & 3, qr = lane >> 2;
    const uint32_t a_base = sbase + AHI_BYTE + (uint32_t)(r0 + (lane & 15)) * ASTRIDE
                          + (uint32_t)(lane >> 4) * 16;
    const int nt0 = nh * 8;

    // ---- layers 1..3 (Wt[0..2], rowdy*gate) + final linear (Wtf) ----
    for (int L = 0; L < 4; ++L) {
        const bool fin = (L == 3);

        float d0[8][4], d1[8][4];
#pragma unroll
        for (int n0 = 0; n0 < 8; ++n0)
#pragma unroll
            for (int c = 0; c < 4; ++c) { d0[n0][c] = 0.f; d1[n0][c] = 0.f; }

        const uint4* __restrict__ wbase = &g_Wfrag[L][0];

        // A-fragment double buffer: prefetch ks=0
        uint32_t ah0[4], al0[4], ah1[4], al1[4];
        uint32_t nah0[4], nal0[4], nah1[4], nal1[4];
        ldmat4(ah0, a_base);
        ldmat4(al0, a_base + ABYTES);
        ldmat4(ah1, a_base + 16 * ASTRIDE);
        ldmat4(al1, a_base + 16 * ASTRIDE + ABYTES);

#pragma unroll 1
        for (int ks = 0; ks < 8; ++ks) {
            // prefetch next iteration's A fragments before the HMMA stream
            if (ks < 7) {
                uint32_t naddr = a_base + (uint32_t)(ks + 1) * 32;
                ldmat4(nah0, naddr);
                ldmat4(nal0, naddr + ABYTES);
                ldmat4(nah1, naddr + 16 * ASTRIDE);
                ldmat4(nal1, naddr + 16 * ASTRIDE + ABYTES);
            }
            const uint4* __restrict__ wrow = wbase + (ks * 16 + nt0) * 32 + lane;
#pragma unroll
            for (int h = 0; h < 2; ++h) {
                uint4 wv[4];
#pragma unroll
                for (int q = 0; q < 4; ++q) wv[q] = __ldg(&wrow[(h * 4 + q) * 32]);
#pragma unroll
                for (int q = 0; q < 4; ++q) {
                    const int n0 = h * 4 + q;
                    hmma(d0[n0], ah0, wv[q].x, wv[q].y);
                    hmma(d0[n0], al0, wv[q].x, wv[q].y);
                    hmma(d0[n0], ah0, wv[q].z, wv[q].w);
                    hmma(d1[n0], ah1, wv[q].x, wv[q].y);
                    hmma(d1[n0], al1, wv[q].x, wv[q].y);
                    hmma(d1[n0], ah1, wv[q].z, wv[q].w);
                }
            }
#pragma unroll
            for (int i = 0; i < 4; ++i) {
                ah0[i] = nah0[i]; al0[i] = nal0[i];
                ah1[i] = nah1[i]; al1[i] = nal1[i];
            }
        }

        const int ra = r0 + qr;          // rows ra, ra+8 (tile0), ra+16, ra+24 (tile1)
        if (!fin) {
            bar64(1 + w4);               // pair {s, s+4}: GEMM reads done before writes
            const int bofs = SBIAS_F + L * 128;
            const int aofs = SAT_F + (L + 1) * 128;
            const int qofs = SWQ_F + (L + 1) * 128;
            const int gofs = SGATE_F + (L + 1) * 128;
#pragma unroll
            for (int n0 = 0; n0 < 8; ++n0) {
                const int cb = (nt0 + n0) * 8 + qm * 2;
                float2 bi = *(const float2*)&sm[bofs + cb];
                float2 av = *(const float2*)&sm[aofs + cb];
                float2 qv = *(const float2*)&sm[qofs + cb];
                float2 gv = *(const float2*)&sm[gofs + cb];
#pragma unroll
                for (int t = 0; t < 2; ++t) {
                    const float* dd = t ? d1[n0] : d0[n0];
                    const int rA = ra + t * 16, rB = rA + 8;
                    float z0 = dd[0] + bi.x, z1 = dd[1] + bi.y;
                    float z2 = dd[2] + bi.x, z3 = dd[3] + bi.y;
                    float v0 = (tanh_ap(z0) + av.x * sin_ap(qv.x * z0)) * gv.x;
                    float v1 = (tanh_ap(z1) + av.y * sin_ap(qv.y * z1)) * gv.y;
                    float v2 = (tanh_ap(z2) + av.x * sin_ap(qv.x * z2)) * gv.x;
                    float v3 = (tanh_ap(z3) + av.y * sin_ap(qv.y * z3)) * gv.y;
                    float h0, l0, h1, l1, h2, l2, h3, l3;
                    split2(v0, h0, l0); split2(v1, h1, l1);
                    split2(v2, h2, l2); split2(v3, h3, l3);
                    *(uint32_t*)(AhiC + rA * ASTRIDE + cb * 2) = pkbf(h0, h1);
                    *(uint32_t*)(AhiC + rB * ASTRIDE + cb * 2) = pkbf(h2, h3);
                    *(uint32_t*)(AloC + rA * ASTRIDE + cb * 2) = pkbf(l0, l1);
                    *(uint32_t*)(AloC + rB * ASTRIDE + cb * 2) = pkbf(l2, l3);
                }
            }
            bar64(1 + w4);               // writes visible before next layer's reads
        } else {
            __syncthreads();             // all GEMM reads done -> reuse A region as fp32
            float* sAct = (float*)(smc + AHI_BYTE);   // [128][132] floats
#pragma unroll
            for (int n0 = 0; n0 < 8; ++n0) {
                const int cb = (nt0 + n0) * 8 + qm * 2;
                float2 bt2 = *(const float2*)&sm[SBIAS_F + 384 + cb];
#pragma unroll
                for (int t = 0; t < 2; ++t) {
                    const float* dd = t ? d1[n0] : d0[n0];
                    const int rA = ra + t * 16, rB = rA + 8;
                    *(float2*)&sAct[rA * 132 + cb] = make_float2(dd[0] + bt2.x, dd[1] + bt2.y);
                    *(float2*)&sAct[rB * 132 + cb] = make_float2(dd[2] + bt2.x, dd[3] + bt2.y);
                }
            }
            __syncthreads();

            // final contraction, split across 2 thread-halves (64 h each)
            {
                const int p  = tid & 127;
                const int hh = tid >> 7;           // 0 or 1
                u64 q0 = 0ull, q1 = 0ull, q2 = 0ull, q3 = 0ull, q4 = 0ull;
                const int hbase = hh * 64;
#pragma unroll 4
                for (int h = hbase; h < hbase + 64; h += 4) {
                    ulonglong2 a  = *(const ulonglong2*)&sAct[p * 132 + h];
                    ulonglong2 c0 = *(const ulonglong2*)&sm[SBC_F + 0 * 128 + h];
                    ulonglong2 c1 = *(const ulonglong2*)&sm[SBC_F + 1 * 128 + h];
                    ulonglong2 c2 = *(const ulonglong2*)&sm[SBC_F + 2 * 128 + h];
                    ulonglong2 c3 = *(const ulonglong2*)&sm[SBC_F + 3 * 128 + h];
                    ulonglong2 c4 = *(const ulonglong2*)&sm[SBC_F + 4 * 128 + h];
                    fma2(q0, a.x, c0.x); fma2(q0, a.y, c0.y);
                    fma2(q1, a.x, c1.x); fma2(q1, a.y, c1.y);
                    fma2(q2, a.x, c2.x); fma2(q2, a.y, c2.y);
                    fma2(q3, a.x, c3.x); fma2(q3, a.y, c3.y);
                    fma2(q4, a.x, c4.x); fma2(q4, a.y, c4.y);
                }
                float2 v0 = up2(q0), v1 = up2(q1), v2 = up2(q2), v3 = up2(q3), v4 = up2(q4);
                float s0 = v0.x + v0.y, s1 = v1.x + v1.y, s2 = v2.x + v2.y;
                float s3 = v3.x + v3.y, s4 = v4.x + v4.y;
                // partials from half 1 go to smem (reuse W0 scalar region, now dead)
                float* red = &sm[SW0_F];           // 128*5 floats needed (640 <= 640 free w/ SB0)
                if (hh == 1) {
                    red[p]       = s0; red[128 + p] = s1; red[256 + p] = s2;
                    red[384 + p] = s3; red[512 + p] = s4;
                }
                __syncthreads();
                if (hh == 0) {
                    const int pglob = p0 + p;
                    if (pglob < NPTS) {
                        float* dst = out + ((size_t)b * NPTS + pglob) * OUTD;
                        dst[0] = s0 + red[p];
                        dst[1] = s1 + red[128 + p];
                        dst[2] = s2 + red[256 + p];
                        dst[3] = s3 + red[384 + p];
                        dst[4] = s4 + red[512 + p];
                    }
                }
            }
        }
    }
}

// ---------------------------------------------------------------------------
extern "C" void kernel_launch(void* const* d_in, const int* in_sizes, int n_in,
                              void* d_out, int out_size)
{
    const float* coords = (const float*)d_in[0];
    const float* sdf    = (const float*)d_in[1];
    const float* params = (const float*)d_in[2];
    const float* Wb0    = (const float*)d_in[3];
    const float* bb0    = (const float*)d_in[4];
    const float* Wb     = (const float*)d_in[5];
    const float* bbv    = (const float*)d_in[6];
    const float* Wbf    = (const float*)d_in[7];
    const float* bbf    = (const float*)d_in[8];
    const float* ab     = (const float*)d_in[9];
    const float* wb     = (const float*)d_in[10];
    const float* Wt0    = (const float*)d_in[11];
    const float* bt0    = (const float*)d_in[12];
    const float* Wt     = (const float*)d_in[13];
    const float* bt     = (const float*)d_in[14];
    const float* Wtf    = (const float*)d_in[15];
    const float* btf    = (const float*)d_in[16];
    const float* at     = (const float*)d_in[17];
    const float* wt     = (const float*)d_in[18];
    float* out = (float*)d_out;

    cudaFuncSetAttribute(trunk_kernel, cudaFuncAttributeMaxDynamicSharedMemorySize, SMEM_BYTES);

    prep_kernel<<<48, 256>>>(Wt, Wtf, params, Wb0, bb0, Wb, bbv, Wbf, bbf, ab, wb);

    dim3 grid(NBLK, BB);
    trunk_kernel<<<grid, THR, SMEM_BYTES>>>(coords, sdf, Wt0, bt0, bt, btf,
                                            at, wt, out);
}

// round 15
// speedup vs baseline: 1.0087x; 1.0087x over previous
#include <cuda_runtime.h>
#include <cuda_bf16.h>
#include <cstdint>
#include <cstddef>

#define BB   16
#define NPTS 10000
#define HID  128
#define OUTD 5
#define THR  192
#define PTS  96
#define NBLK 105            // ceil(10000/96)

// scalar region (float indices into sm[])
#define SX_F    0           // 96*4 = 384 (pad to 512)
#define SGATE_F 512         // 4*128
#define SBC_F   1024        // 5*128
#define SBIAS_F 1664        // bt (3*128) + btf (128)
#define SAT_F   2176
#define SWQ_F   2688
#define SW0_F   3200
#define SB0_F   3712        // 128 -> scalar region ends 3840 floats = 15360 B
// byte regions
#define AHI_BYTE 15360      // A hi tile: 96 rows * 272B = 26112
#define ALO_BYTE 41472      // A lo tile
#define ABYTES   26112
#define ASTRIDE  272        // 136 bf16 per row
#define SMEM_BYTES 67584

typedef unsigned long long u64;

__device__ float g_gate[BB * 4 * HID];
__device__ float g_bc[BB * OUTD * HID];
__device__ __align__(16) uint4 g_Wfrag[4][4096];   // [layer][(ks*16+n0)*32+lane]

__device__ __forceinline__ float tanh_ap(float x) {
    float r; asm("tanh.approx.f32 %0, %1;" : "=f"(r) : "f"(x)); return r;
}
__device__ __forceinline__ float sin_ap(float x) {
    float r; asm("sin.approx.f32 %0, %1;" : "=f"(r) : "f"(x)); return r;
}
__device__ __forceinline__ uint32_t smem_u32(const void* p) {
    uint32_t a;
    asm("{ .reg .u64 t; cvta.to.shared.u64 t, %1; cvt.u32.u64 %0, t; }" : "=r"(a) : "l"(p));
    return a;
}
__device__ __forceinline__ uint32_t pkbf(float e0, float e1) {
    uint32_t r; asm("cvt.rn.satfinite.bf16x2.f32 %0, %1, %2;" : "=r"(r) : "f"(e1), "f"(e0));
    return r;
}
__device__ __forceinline__ void split2(float v, float& hf, float& lf) {
    __nv_bfloat16 h = __float2bfloat16_rn(v);
    hf = __bfloat162float(h);
    lf = v - hf;
}
__device__ __forceinline__ void ldmat4(uint32_t* r, uint32_t addr) {
    asm volatile("ldmatrix.sync.aligned.m8n8.x4.shared.b16 {%0,%1,%2,%3}, [%4];"
                 : "=r"(r[0]), "=r"(r[1]), "=r"(r[2]), "=r"(r[3]) : "r"(addr));
}
__device__ __forceinline__ void hmma(float (&d)[4], const uint32_t* a, uint32_t b0, uint32_t b1) {
    asm volatile(
        "mma.sync.aligned.m16n8k16.row.col.f32.bf16.bf16.f32 "
        "{%0,%1,%2,%3}, {%4,%5,%6,%7}, {%8,%9}, {%0,%1,%2,%3};"
        : "+f"(d[0]), "+f"(d[1]), "+f"(d[2]), "+f"(d[3])
        : "r"(a[0]), "r"(a[1]), "r"(a[2]), "r"(a[3]), "r"(b0), "r"(b1));
}
__device__ __forceinline__ void fma2(u64& d, u64 a, u64 b) {
    asm("fma.rn.f32x2 %0, %1, %2, %0;" : "+l"(d) : "l"(a), "l"(b));
}
__device__ __forceinline__ float2 up2(u64 v) {
    float2 r; asm("mov.b64 {%0, %1}, %2;" : "=f"(r.x), "=f"(r.y) : "l"(v)); return r;
}
__device__ __forceinline__ void bar64(int id) {
    asm volatile("bar.sync %0, 64;" :: "r"(id) : "memory");
}

// ---------------------------------------------------------------------------
// Fused prep: blocks 0..31 pack W fragments; blocks 32..47 branch MLP.
// ---------------------------------------------------------------------------
__global__ void prep_kernel(const float* __restrict__ Wt,  const float* __restrict__ Wtf,
                            const float* __restrict__ params,
                            const float* __restrict__ Wb0, const float* __restrict__ bb0,
                            const float* __restrict__ Wb,  const float* __restrict__ bbv,
                            const float* __restrict__ Wbf, const float* __restrict__ bbf,
                            const float* __restrict__ ab,  const float* __restrict__ wb)
{
    if (blockIdx.x < 32) {
        const int l = blockIdx.x >> 3, chunk = blockIdx.x & 7;
        const float* W = (l < 3) ? (Wt + (size_t)l * HID * HID) : Wtf;
        const int e0 = chunk * 512;
        for (int e = e0 + threadIdx.x; e < e0 + 512; e += 256) {
            int ks = e >> 9, n0 = (e >> 5) & 15, t = e & 31;
            int n  = n0 * 8 + (t >> 2);
            int kb = ks * 16 + (t & 3) * 2;
            float w00 = W[(size_t)kb * HID + n],       w01 = W[(size_t)(kb + 1) * HID + n];
            float w10 = W[(size_t)(kb + 8) * HID + n], w11 = W[(size_t)(kb + 9) * HID + n];
            float h00, l00, h01, l01, h10, l10, h11, l11;
            split2(w00, h00, l00); split2(w01, h01, l01);
            split2(w10, h10, l10); split2(w11, h11, l11);
            uint4 u;
            u.x = pkbf(h00, h01); u.y = pkbf(h10, h11);
            u.z = pkbf(l00, l01); u.w = pkbf(l10, l11);
            g_Wfrag[l][e] = u;
        }
        return;
    }

    // ---- branch MLP ----
    __shared__ float h_s[HID];
    __shared__ float part[HID];
    const int b = blockIdx.x - 32, tid = threadIdx.x;
    const int j = tid & 127, hh = tid >> 7;

    float g = 0.f;
    if (hh == 0) {
        float z = bb0[j];
#pragma unroll
        for (int c = 0; c < 6; ++c) z = fmaf(params[b * 6 + c], Wb0[c * HID + j], z);
        float v = tanh_ap(z) + ab[j] * sin_ap(wb[j] * z);
        g = v; g_gate[(b * 4) * HID + j] = g; h_s[j] = v;
    }
    __syncthreads();

    for (int i = 0; i < 3; ++i) {
        const float* W = Wb + (size_t)i * HID * HID;
        float zz = (hh == 0) ? bbv[i * HID + j] : 0.f;
        const int k0 = hh * 64;
#pragma unroll 4
        for (int k = 0; k < 64; ++k) zz = fmaf(h_s[k0 + k], W[(size_t)(k0 + k) * HID + j], zz);
        if (hh) part[j] = zz;
        __syncthreads();
        float v = 0.f;
        if (hh == 0) {
            float z = zz + part[j];
            v = tanh_ap(z) + ab[(i + 1) * HID + j] * sin_ap(wb[(i + 1) * HID + j] * z);
            g += v; g_gate[(b * 4 + i + 1) * HID + j] = g;
        }
        __syncthreads();
        if (hh == 0) h_s[j] = v;
        __syncthreads();
    }

#pragma unroll
    for (int o = 0; o < OUTD; ++o) {
        float zz = (hh == 0) ? bbf[o * HID + j] : 0.f;
        const int k0 = hh * 64;
#pragma unroll 4
        for (int k = 0; k < 64; ++k)
            zz = fmaf(h_s[k0 + k], Wbf[(size_t)(k0 + k) * (HID * OUTD) + o * HID + j], zz);
        if (hh) part[j] = zz;
        __syncthreads();
        if (hh == 0) g_bc[(b * OUTD + o) * HID + j] = zz + part[j];
        __syncthreads();
    }
}

// ---------------------------------------------------------------------------
// Trunk: 96 pts/block, 6 warps, 2 blocks/SM. Warp pair (s, s+3) owns rows
// 32s..32s+31: warp s cols 0..63, warp s+3 cols 64..127. Same per-warp tile
// as R13 (M=32 x N=64, wf-optimal); smaller tile cuts the tail wave 17%->6%.
// ---------------------------------------------------------------------------
__global__ void __launch_bounds__(THR, 2)
trunk_kernel(const float* __restrict__ coords, const float* __restrict__ sdf,
             const float* __restrict__ Wt0, const float* __restrict__ bt0,
             const float* __restrict__ btv, const float* __restrict__ btf,
             const float* __restrict__ at,  const float* __restrict__ wt,
             float* __restrict__ out)
{
    extern __shared__ float sm[];
    char* smc = (char*)sm;
    const uint32_t sbase = smem_u32(sm);

    const int b    = blockIdx.y;
    const int p0   = blockIdx.x * PTS;
    const int tid  = threadIdx.x;
    const int warp = tid >> 5;
    const int lane = tid & 31;
    const int strip = (warp < 3) ? warp : (warp - 3);   // 0..2
    const int nh    = (warp < 3) ? 0 : 1;               // n-half

    // stage inputs + scalars
    if (tid < PTS) {
        int p = p0 + tid;
        float4 v = make_float4(0.f, 0.f, 0.f, 0.f);
        if (p < NPTS) {
            const float* c = coords + ((size_t)b * NPTS + p) * 3;
            v.x = c[0]; v.y = c[1]; v.z = c[2];
            v.w = sdf[(size_t)b * NPTS + p];
        }
        ((float4*)&sm[SX_F])[tid] = v;
    }
    for (int i = tid; i < 512; i += THR) sm[SGATE_F + i] = g_gate[b * 512 + i];
    for (int i = tid; i < 640; i += THR) sm[SBC_F + i]   = g_bc[b * 640 + i];
    for (int i = tid; i < 384; i += THR) sm[SBIAS_F + i] = btv[i];
    for (int i = tid; i < 128; i += THR) sm[SBIAS_F + 384 + i] = btf[i];
    for (int i = tid; i < 512; i += THR) sm[SAT_F + i] = at[i];
    for (int i = tid; i < 512; i += THR) sm[SWQ_F + i] = wt[i];
    for (int i = tid; i < 512; i += THR) sm[SW0_F + i] = Wt0[i];
    for (int i = tid; i < 128; i += THR) sm[SB0_F + i] = bt0[i];
    __syncthreads();

    char* AhiC = smc + AHI_BYTE;
    char* AloC = smc + ALO_BYTE;

    // ---- layer 0: thread handles point r=tid/2, column half ch=tid&1 ----
    {
        const int r = tid >> 1, ch = tid & 1;
        float4 xv = ((float4*)&sm[SX_F])[r];
#pragma unroll 1
        for (int j0 = ch * 64; j0 < ch * 64 + 64; j0 += 8) {
            float hf[8], lf[8];
#pragma unroll
            for (int jj = 0; jj < 8; ++jj) {
                int j = j0 + jj;
                float z = fmaf(xv.x, sm[SW0_F + j],
                          fmaf(xv.y, sm[SW0_F + 128 + j],
                          fmaf(xv.z, sm[SW0_F + 256 + j],
                          fmaf(xv.w, sm[SW0_F + 384 + j], sm[SB0_F + j]))));
                float v = (tanh_ap(z) + sm[SAT_F + j] * sin_ap(sm[SWQ_F + j] * z)) * sm[SGATE_F + j];
                split2(v, hf[jj], lf[jj]);
            }
            uint4 hq, lq;
            hq.x = pkbf(hf[0], hf[1]); hq.y = pkbf(hf[2], hf[3]);
            hq.z = pkbf(hf[4], hf[5]); hq.w = pkbf(hf[6], hf[7]);
            lq.x = pkbf(lf[0], lf[1]); lq.y = pkbf(lf[2], lf[3]);
            lq.z = pkbf(lf[4], lf[5]); lq.w = pkbf(lf[6], lf[7]);
            *(uint4*)(AhiC + r * ASTRIDE + j0 * 2) = hq;
            *(uint4*)(AloC + r * ASTRIDE + j0 * 2) = lq;
        }
    }
    __syncthreads();                     // layer-0 writes visible to all pairs

    const int r0 = strip * 32;
    const int qm = lane & 3, qr = lane >> 2;
    const uint32_t a_base = sbase + AHI_BYTE + (uint32_t)(r0 + (lane & 15)) * ASTRIDE
                          + (uint32_t)(lane >> 4) * 16;
    const int nt0 = nh * 8;

    // ---- layers 1..3 (Wt[0..2], rowdy*gate) + final linear (Wtf) ----
    for (int L = 0; L < 4; ++L) {
        const bool fin = (L == 3);

        float d0[8][4], d1[8][4];
#pragma unroll
        for (int n0 = 0; n0 < 8; ++n0)
#pragma unroll
            for (int c = 0; c < 4; ++c) { d0[n0][c] = 0.f; d1[n0][c] = 0.f; }

        const uint4* __restrict__ wbase = &g_Wfrag[L][0];
#pragma unroll 1
        for (int ks = 0; ks < 8; ++ks) {
            uint32_t ah0[4], al0[4], ah1[4], al1[4];
            uint32_t aaddr = a_base + (uint32_t)ks * 32;
            ldmat4(ah0, aaddr);
            ldmat4(al0, aaddr + ABYTES);
            ldmat4(ah1, aaddr + 16 * ASTRIDE);
            ldmat4(al1, aaddr + 16 * ASTRIDE + ABYTES);
            const uint4* __restrict__ wrow = wbase + (ks * 16 + nt0) * 32 + lane;
#pragma unroll
            for (int h = 0; h < 2; ++h) {
                uint4 wv[4];
#pragma unroll
                for (int q = 0; q < 4; ++q) wv[q] = __ldg(&wrow[(h * 4 + q) * 32]);
#pragma unroll
                for (int q = 0; q < 4; ++q) {
                    const int n0 = h * 4 + q;
                    hmma(d0[n0], ah0, wv[q].x, wv[q].y);
                    hmma(d0[n0], al0, wv[q].x, wv[q].y);
                    hmma(d0[n0], ah0, wv[q].z, wv[q].w);
                    hmma(d1[n0], ah1, wv[q].x, wv[q].y);
                    hmma(d1[n0], al1, wv[q].x, wv[q].y);
                    hmma(d1[n0], ah1, wv[q].z, wv[q].w);
                }
            }
        }

        const int ra = r0 + qr;          // rows ra, ra+8 (tile0), ra+16, ra+24 (tile1)
        if (!fin) {
            bar64(1 + strip);            // pair {s, s+3}: GEMM reads done before writes
            const int bofs = SBIAS_F + L * 128;
            const int aofs = SAT_F + (L + 1) * 128;
            const int qofs = SWQ_F + (L + 1) * 128;
            const int gofs = SGATE_F + (L + 1) * 128;
#pragma unroll
            for (int n0 = 0; n0 < 8; ++n0) {
                const int cb = (nt0 + n0) * 8 + qm * 2;
                float2 bi = *(const float2*)&sm[bofs + cb];
                float2 av = *(const float2*)&sm[aofs + cb];
                float2 qv = *(const float2*)&sm[qofs + cb];
                float2 gv = *(const float2*)&sm[gofs + cb];
#pragma unroll
                for (int t = 0; t < 2; ++t) {
                    const float* dd = t ? d1[n0] : d0[n0];
                    const int rA = ra + t * 16, rB = rA + 8;
                    float z0 = dd[0] + bi.x, z1 = dd[1] + bi.y;
                    float z2 = dd[2] + bi.x, z3 = dd[3] + bi.y;
                    float v0 = (tanh_ap(z0) + av.x * sin_ap(qv.x * z0)) * gv.x;
                    float v1 = (tanh_ap(z1) + av.y * sin_ap(qv.y * z1)) * gv.y;
                    float v2 = (tanh_ap(z2) + av.x * sin_ap(qv.x * z2)) * gv.x;
                    float v3 = (tanh_ap(z3) + av.y * sin_ap(qv.y * z3)) * gv.y;
                    float h0, l0, h1, l1, h2, l2, h3, l3;
                    split2(v0, h0, l0); split2(v1, h1, l1);
                    split2(v2, h2, l2); split2(v3, h3, l3);
                    *(uint32_t*)(AhiC + rA * ASTRIDE + cb * 2) = pkbf(h0, h1);
                    *(uint32_t*)(AhiC + rB * ASTRIDE + cb * 2) = pkbf(h2, h3);
                    *(uint32_t*)(AloC + rA * ASTRIDE + cb * 2) = pkbf(l0, l1);
                    *(uint32_t*)(AloC + rB * ASTRIDE + cb * 2) = pkbf(l2, l3);
                }
            }
            bar64(1 + strip);            // writes visible before next layer's reads
        } else {
            __syncthreads();             // all GEMM reads done -> reuse A region as fp32
            float* sAct = (float*)(smc + AHI_BYTE);   // [96][132] floats
#pragma unroll
            for (int n0 = 0; n0 < 8; ++n0) {
                const int cb = (nt0 + n0) * 8 + qm * 2;
                float2 bt2 = *(const float2*)&sm[SBIAS_F + 384 + cb];
#pragma unroll
                for (int t = 0; t < 2; ++t) {
                    const float* dd = t ? d1[n0] : d0[n0];
                    const int rA = ra + t * 16, rB = rA + 8;
                    *(float2*)&sAct[rA * 132 + cb] = make_float2(dd[0] + bt2.x, dd[1] + bt2.y);
                    *(float2*)&sAct[rB * 132 + cb] = make_float2(dd[2] + bt2.x, dd[3] + bt2.y);
                }
            }
            __syncthreads();

            // final contraction: 192 threads = 96 points x 2 h-halves
            {
                const int hh = (tid >= PTS) ? 1 : 0;
                const int p  = tid - hh * PTS;
                u64 q0 = 0ull, q1 = 0ull, q2 = 0ull, q3 = 0ull, q4 = 0ull;
                const int hbase = hh * 64;
#pragma unroll 4
                for (int h = hbase; h < hbase + 64; h += 4) {
                    ulonglong2 a  = *(const ulonglong2*)&sAct[p * 132 + h];
                    ulonglong2 c0 = *(const ulonglong2*)&sm[SBC_F + 0 * 128 + h];
                    ulonglong2 c1 = *(const ulonglong2*)&sm[SBC_F + 1 * 128 + h];
                    ulonglong2 c2 = *(const ulonglong2*)&sm[SBC_F + 2 * 128 + h];
                    ulonglong2 c3 = *(const ulonglong2*)&sm[SBC_F + 3 * 128 + h];
                    ulonglong2 c4 = *(const ulonglong2*)&sm[SBC_F + 4 * 128 + h];
                    fma2(q0, a.x, c0.x); fma2(q0, a.y, c0.y);
                    fma2(q1, a.x, c1.x); fma2(q1, a.y, c1.y);
                    fma2(q2, a.x, c2.x); fma2(q2, a.y, c2.y);
                    fma2(q3, a.x, c3.x); fma2(q3, a.y, c3.y);
                    fma2(q4, a.x, c4.x); fma2(q4, a.y, c4.y);
                }
                float2 v0 = up2(q0), v1 = up2(q1), v2 = up2(q2), v3 = up2(q3), v4 = up2(q4);
                float s0 = v0.x + v0.y, s1 = v1.x + v1.y, s2 = v2.x + v2.y;
                float s3 = v3.x + v3.y, s4 = v4.x + v4.y;
                float* red = &sm[SW0_F];          // 96*5 = 480 floats (region dead)
                if (hh == 1) {
                    red[p]       = s0; red[96 + p]  = s1; red[192 + p] = s2;
                    red[288 + p] = s3; red[384 + p] = s4;
                }
                __syncthreads();
                if (hh == 0) {
                    const int pglob = p0 + p;
                    if (pglob < NPTS) {
                        float* dst = out + ((size_t)b * NPTS + pglob) * OUTD;
                        dst[0] = s0 + red[p];
                        dst[1] = s1 + red[96 + p];
                        dst[2] = s2 + red[192 + p];
                        dst[3] = s3 + red[288 + p];
                        dst[4] = s4 + red[384 + p];
                    }
                }
            }
        }
    }
}

// ---------------------------------------------------------------------------
extern "C" void kernel_launch(void* const* d_in, const int* in_sizes, int n_in,
                              void* d_out, int out_size)
{
    const float* coords = (const float*)d_in[0];
    const float* sdf    = (const float*)d_in[1];
    const float* params = (const float*)d_in[2];
    const float* Wb0    = (const float*)d_in[3];
    const float* bb0    = (const float*)d_in[4];
    const float* Wb     = (const float*)d_in[5];
    const float* bbv    = (const float*)d_in[6];
    const float* Wbf    = (const float*)d_in[7];
    const float* bbf    = (const float*)d_in[8];
    const float* ab     = (const float*)d_in[9];
    const float* wb     = (const float*)d_in[10];
    const float* Wt0    = (const float*)d_in[11];
    const float* bt0    = (const float*)d_in[12];
    const float* Wt     = (const float*)d_in[13];
    const float* bt     = (const float*)d_in[14];
    const float* Wtf    = (const float*)d_in[15];
    const float* btf    = (const float*)d_in[16];
    const float* at     = (const float*)d_in[17];
    const float* wt     = (const float*)d_in[18];
    float* out = (float*)d_out;

    cudaFuncSetAttribute(trunk_kernel, cudaFuncAttributeMaxDynamicSharedMemorySize, SMEM_BYTES);

    prep_kernel<<<48, 256>>>(Wt, Wtf, params, Wb0, bb0, Wb, bbv, Wbf, bbf, ab, wb);

    dim3 grid(NBLK, BB);
    trunk_kernel<<<grid, THR, SMEM_BYTES>>>(coords, sdf, Wt0, bt0, bt, btf,
                                            at, wt, out);
}

// round 16
// speedup vs baseline: 1.3360x; 1.3244x over previous
#include <cuda_runtime.h>
#include <cuda_bf16.h>
#include <cuda_fp16.h>
#include <cstdint>
#include <cstddef>

#define BB   16
#define NPTS 10000
#define HID  128
#define OUTD 5
#define THR  256
#define PTS  128
#define NBLK 79             // ceil(10000/128)

// scalar region (float indices into sm[])
#define SX_F    0           // 128*4
#define SGATE_F 512         // 4*128
#define SBC_F   1024        // 5*128
#define SBIAS_F 1664        // bt (3*128) + btf (128)
#define SAT_F   2176
#define SWQ_F   2688
#define SW0_F   3200
#define SB0_F   3712        // 128 -> scalar region ends at 3840 floats = 15360 B
// byte regions
#define AHI_BYTE 15360      // A hi tile: 128 rows * 272B = 34816
#define ALO_BYTE 50176      // A lo tile
#define ABYTES   34816
#define ASTRIDE  272        // 136 fp16 per row
#define SMEM_BYTES 84992

typedef unsigned long long u64;

__device__ float g_gate[BB * 4 * HID];
__device__ float g_bc[BB * OUTD * HID];
__device__ __align__(8) uint2 g_Wfrag[4][4096];    // fp16 frags [layer][(ks*16+n0)*32+lane]

__device__ __forceinline__ float tanh_ap(float x) {
    float r; asm("tanh.approx.f32 %0, %1;" : "=f"(r) : "f"(x)); return r;
}
__device__ __forceinline__ float sin_ap(float x) {
    float r; asm("sin.approx.f32 %0, %1;" : "=f"(r) : "f"(x)); return r;
}
__device__ __forceinline__ uint32_t smem_u32(const void* p) {
    uint32_t a;
    asm("{ .reg .u64 t; cvta.to.shared.u64 t, %1; cvt.u32.u64 %0, t; }" : "=r"(a) : "l"(p));
    return a;
}
// pack two f32 -> f16x2; e0 -> low half (smaller k), e1 -> high half
__device__ __forceinline__ uint32_t pkhf(float e0, float e1) {
    uint32_t r; asm("cvt.rn.f16x2.f32 %0, %1, %2;" : "=r"(r) : "f"(e1), "f"(e0));
    return r;
}
__device__ __forceinline__ void split2h(float v, float& hf, float& lf) {
    __half h = __float2half_rn(v);
    hf = __half2float(h);
    lf = v - hf;
}
__device__ __forceinline__ void ldmat4(uint32_t* r, uint32_t addr) {
    asm volatile("ldmatrix.sync.aligned.m8n8.x4.shared.b16 {%0,%1,%2,%3}, [%4];"
                 : "=r"(r[0]), "=r"(r[1]), "=r"(r[2]), "=r"(r[3]) : "r"(addr));
}
__device__ __forceinline__ void hmma(float (&d)[4], const uint32_t* a, uint32_t b0, uint32_t b1) {
    asm volatile(
        "mma.sync.aligned.m16n8k16.row.col.f32.f16.f16.f32 "
        "{%0,%1,%2,%3}, {%4,%5,%6,%7}, {%8,%9}, {%0,%1,%2,%3};"
        : "+f"(d[0]), "+f"(d[1]), "+f"(d[2]), "+f"(d[3])
        : "r"(a[0]), "r"(a[1]), "r"(a[2]), "r"(a[3]), "r"(b0), "r"(b1));
}
__device__ __forceinline__ void fma2(u64& d, u64 a, u64 b) {
    asm("fma.rn.f32x2 %0, %1, %2, %0;" : "+l"(d) : "l"(a), "l"(b));
}
__device__ __forceinline__ float2 up2(u64 v) {
    float2 r; asm("mov.b64 {%0, %1}, %2;" : "=f"(r.x), "=f"(r.y) : "l"(v)); return r;
}
__device__ __forceinline__ void bar64(int id) {
    asm volatile("bar.sync %0, 64;" :: "r"(id) : "memory");
}

// ---------------------------------------------------------------------------
// Fused prep: blocks 0..63 pack fp16 W fragments (4 layers x 16 chunks of 256
// elems, one elem/thread); blocks 64..79 run the branch MLP.
// ---------------------------------------------------------------------------
__global__ void prep_kernel(const float* __restrict__ Wt,  const float* __restrict__ Wtf,
                            const float* __restrict__ params,
                            const float* __restrict__ Wb0, const float* __restrict__ bb0,
                            const float* __restrict__ Wb,  const float* __restrict__ bbv,
                            const float* __restrict__ Wbf, const float* __restrict__ bbf,
                            const float* __restrict__ ab,  const float* __restrict__ wb)
{
    if (blockIdx.x < 64) {
        const int l = blockIdx.x >> 4, chunk = blockIdx.x & 15;
        const float* W = (l < 3) ? (Wt + (size_t)l * HID * HID) : Wtf;
        const int e = chunk * 256 + threadIdx.x;
        int ks = e >> 9, n0 = (e >> 5) & 15, t = e & 31;
        int n  = n0 * 8 + (t >> 2);
        int kb = ks * 16 + (t & 3) * 2;
        float w00 = W[(size_t)kb * HID + n],       w01 = W[(size_t)(kb + 1) * HID + n];
        float w10 = W[(size_t)(kb + 8) * HID + n], w11 = W[(size_t)(kb + 9) * HID + n];
        uint2 u;
        u.x = pkhf(w00, w01);
        u.y = pkhf(w10, w11);
        g_Wfrag[l][e] = u;
        return;
    }

    // ---- branch MLP ----
    __shared__ float h_s[HID];
    __shared__ float part[HID];
    const int b = blockIdx.x - 64, tid = threadIdx.x;
    const int j = tid & 127, hh = tid >> 7;

    float g = 0.f;
    if (hh == 0) {
        float z = bb0[j];
#pragma unroll
        for (int c = 0; c < 6; ++c) z = fmaf(params[b * 6 + c], Wb0[c * HID + j], z);
        float v = tanh_ap(z) + ab[j] * sin_ap(wb[j] * z);
        g = v; g_gate[(b * 4) * HID + j] = g; h_s[j] = v;
    }
    __syncthreads();

    for (int i = 0; i < 3; ++i) {
        const float* W = Wb + (size_t)i * HID * HID;
        float zz = (hh == 0) ? bbv[i * HID + j] : 0.f;
        const int k0 = hh * 64;
#pragma unroll 4
        for (int k = 0; k < 64; ++k) zz = fmaf(h_s[k0 + k], W[(size_t)(k0 + k) * HID + j], zz);
        if (hh) part[j] = zz;
        __syncthreads();
        float v = 0.f;
        if (hh == 0) {
            float z = zz + part[j];
            v = tanh_ap(z) + ab[(i + 1) * HID + j] * sin_ap(wb[(i + 1) * HID + j] * z);
            g += v; g_gate[(b * 4 + i + 1) * HID + j] = g;
        }
        __syncthreads();
        if (hh == 0) h_s[j] = v;
        __syncthreads();
    }

#pragma unroll
    for (int o = 0; o < OUTD; ++o) {
        float zz = (hh == 0) ? bbf[o * HID + j] : 0.f;
        const int k0 = hh * 64;
#pragma unroll 4
        for (int k = 0; k < 64; ++k)
            zz = fmaf(h_s[k0 + k], Wbf[(size_t)(k0 + k) * (HID * OUTD) + o * HID + j], zz);
        if (hh) part[j] = zz;
        __syncthreads();
        if (hh == 0) g_bc[(b * OUTD + o) * HID + j] = zz + part[j];
        __syncthreads();
    }
}

// ---------------------------------------------------------------------------
// Trunk: 128 pts/block, 8 warps, 2 blocks/SM. Warp pair (s, s+4) owns rows
// 32s..32s+31: warp s cols 0..63, warp s+4 cols 64..127. fp16 2-pass GEMM:
// A split exactly into fp16 hi+lo, W single fp16 (4 HMMA per n-tile per ks).
// ---------------------------------------------------------------------------
__global__ void __launch_bounds__(THR, 2)
trunk_kernel(const float* __restrict__ coords, const float* __restrict__ sdf,
             const float* __restrict__ Wt0, const float* __restrict__ bt0,
             const float* __restrict__ btv, const float* __restrict__ btf,
             const float* __restrict__ at,  const float* __restrict__ wt,
             float* __restrict__ out)
{
    extern __shared__ float sm[];
    char* smc = (char*)sm;
    const uint32_t sbase = smem_u32(sm);

    const int b    = blockIdx.y;
    const int p0   = blockIdx.x * PTS;
    const int tid  = threadIdx.x;
    const int warp = tid >> 5;
    const int lane = tid & 31;
    const int w4   = warp & 3;          // row-strip id (32 rows)
    const int nh   = warp >> 2;         // n-half

    // stage inputs + scalars
    if (tid < PTS) {
        int p = p0 + tid;
        float4 v = make_float4(0.f, 0.f, 0.f, 0.f);
        if (p < NPTS) {
            const float* c = coords + ((size_t)b * NPTS + p) * 3;
            v.x = c[0]; v.y = c[1]; v.z = c[2];
            v.w = sdf[(size_t)b * NPTS + p];
        }
        ((float4*)&sm[SX_F])[tid] = v;
    }
    for (int i = tid; i < 512; i += THR) sm[SGATE_F + i] = g_gate[b * 512 + i];
    for (int i = tid; i < 640; i += THR) sm[SBC_F + i]   = g_bc[b * 640 + i];
    for (int i = tid; i < 384; i += THR) sm[SBIAS_F + i] = btv[i];
    for (int i = tid; i < 128; i += THR) sm[SBIAS_F + 384 + i] = btf[i];
    for (int i = tid; i < 512; i += THR) sm[SAT_F + i] = at[i];
    for (int i = tid; i < 512; i += THR) sm[SWQ_F + i] = wt[i];
    for (int i = tid; i < 512; i += THR) sm[SW0_F + i] = Wt0[i];
    for (int i = tid; i < 128; i += THR) sm[SB0_F + i] = bt0[i];
    __syncthreads();

    char* AhiC = smc + AHI_BYTE;
    char* AloC = smc + ALO_BYTE;

    // ---- layer 0: thread handles point r=tid/2, column half ch=tid&1 ----
    {
        const int r = tid >> 1, ch = tid & 1;
        float4 xv = ((float4*)&sm[SX_F])[r];
#pragma unroll 1
        for (int j0 = ch * 64; j0 < ch * 64 + 64; j0 += 8) {
            float hf[8], lf[8];
#pragma unroll
            for (int jj = 0; jj < 8; ++jj) {
                int j = j0 + jj;
                float z = fmaf(xv.x, sm[SW0_F + j],
                          fmaf(xv.y, sm[SW0_F + 128 + j],
                          fmaf(xv.z, sm[SW0_F + 256 + j],
                          fmaf(xv.w, sm[SW0_F + 384 + j], sm[SB0_F + j]))));
                float v = (tanh_ap(z) + sm[SAT_F + j] * sin_ap(sm[SWQ_F + j] * z)) * sm[SGATE_F + j];
                split2h(v, hf[jj], lf[jj]);
            }
            uint4 hq, lq;
            hq.x = pkhf(hf[0], hf[1]); hq.y = pkhf(hf[2], hf[3]);
            hq.z = pkhf(hf[4], hf[5]); hq.w = pkhf(hf[6], hf[7]);
            lq.x = pkhf(lf[0], lf[1]); lq.y = pkhf(lf[2], lf[3]);
            lq.z = pkhf(lf[4], lf[5]); lq.w = pkhf(lf[6], lf[7]);
            *(uint4*)(AhiC + r * ASTRIDE + j0 * 2) = hq;
            *(uint4*)(AloC + r * ASTRIDE + j0 * 2) = lq;
        }
    }
    __syncthreads();                     // layer-0 writes visible to all pairs

    const int r0 = w4 * 32;
    const int qm = lane & 3, qr = lane >> 2;
    const uint32_t a_base = sbase + AHI_BYTE + (uint32_t)(r0 + (lane & 15)) * ASTRIDE
                          + (uint32_t)(lane >> 4) * 16;
    const int nt0 = nh * 8;

    // ---- layers 1..3 (Wt[0..2], rowdy*gate) + final linear (Wtf) ----
    for (int L = 0; L < 4; ++L) {
        const bool fin = (L == 3);

        float d0[8][4], d1[8][4];
#pragma unroll
        for (int n0 = 0; n0 < 8; ++n0)
#pragma unroll
            for (int c = 0; c < 4; ++c) { d0[n0][c] = 0.f; d1[n0][c] = 0.f; }

        const uint2* __restrict__ wbase = &g_Wfrag[L][0];
#pragma unroll 1
        for (int ks = 0; ks < 8; ++ks) {
            uint32_t ah0[4], al0[4], ah1[4], al1[4];
            uint32_t aaddr = a_base + (uint32_t)ks * 32;
            ldmat4(ah0, aaddr);
            ldmat4(al0, aaddr + ABYTES);
            ldmat4(ah1, aaddr + 16 * ASTRIDE);
            ldmat4(al1, aaddr + 16 * ASTRIDE + ABYTES);
            const uint2* __restrict__ wrow = wbase + (ks * 16 + nt0) * 32 + lane;
#pragma unroll
            for (int h = 0; h < 2; ++h) {
                uint2 wv[4];
#pragma unroll
                for (int q = 0; q < 4; ++q) wv[q] = __ldg(&wrow[(h * 4 + q) * 32]);
#pragma unroll
                for (int q = 0; q < 4; ++q) {
                    const int n0 = h * 4 + q;
                    hmma(d0[n0], ah0, wv[q].x, wv[q].y);   // Ahi * W
                    hmma(d0[n0], al0, wv[q].x, wv[q].y);   // Alo * W
                    hmma(d1[n0], ah1, wv[q].x, wv[q].y);
                    hmma(d1[n0], al1, wv[q].x, wv[q].y);
                }
            }
        }

        const int ra = r0 + qr;          // rows ra, ra+8 (tile0), ra+16, ra+24 (tile1)
        if (!fin) {
            bar64(1 + w4);               // pair {s, s+4}: GEMM reads done before writes
            const int bofs = SBIAS_F + L * 128;
            const int aofs = SAT_F + (L + 1) * 128;
            const int qofs = SWQ_F + (L + 1) * 128;
            const int gofs = SGATE_F + (L + 1) * 128;
#pragma unroll
            for (int n0 = 0; n0 < 8; ++n0) {
                const int cb = (nt0 + n0) * 8 + qm * 2;
                float2 bi = *(const float2*)&sm[bofs + cb];
                float2 av = *(const float2*)&sm[aofs + cb];
                float2 qv = *(const float2*)&sm[qofs + cb];
                float2 gv = *(const float2*)&sm[gofs + cb];
#pragma unroll
                for (int t = 0; t < 2; ++t) {
                    const float* dd = t ? d1[n0] : d0[n0];
                    const int rA = ra + t * 16, rB = rA + 8;
                    float z0 = dd[0] + bi.x, z1 = dd[1] + bi.y;
                    float z2 = dd[2] + bi.x, z3 = dd[3] + bi.y;
                    float v0 = (tanh_ap(z0) + av.x * sin_ap(qv.x * z0)) * gv.x;
                    float v1 = (tanh_ap(z1) + av.y * sin_ap(qv.y * z1)) * gv.y;
                    float v2 = (tanh_ap(z2) + av.x * sin_ap(qv.x * z2)) * gv.x;
                    float v3 = (tanh_ap(z3) + av.y * sin_ap(qv.y * z3)) * gv.y;
                    float h0, l0, h1, l1, h2, l2, h3, l3;
                    split2h(v0, h0, l0); split2h(v1, h1, l1);
                    split2h(v2, h2, l2); split2h(v3, h3, l3);
                    *(uint32_t*)(AhiC + rA * ASTRIDE + cb * 2) = pkhf(h0, h1);
                    *(uint32_t*)(AhiC + rB * ASTRIDE + cb * 2) = pkhf(h2, h3);
                    *(uint32_t*)(AloC + rA * ASTRIDE + cb * 2) = pkhf(l0, l1);
                    *(uint32_t*)(AloC + rB * ASTRIDE + cb * 2) = pkhf(l2, l3);
                }
            }
            bar64(1 + w4);               // writes visible before next layer's reads
        } else {
            __syncthreads();             // all GEMM reads done -> reuse A region as fp32
            float* sAct = (float*)(smc + AHI_BYTE);   // [128][132] floats
#pragma unroll
            for (int n0 = 0; n0 < 8; ++n0) {
                const int cb = (nt0 + n0) * 8 + qm * 2;
                float2 bt2 = *(const float2*)&sm[SBIAS_F + 384 + cb];
#pragma unroll
                for (int t = 0; t < 2; ++t) {
                    const float* dd = t ? d1[n0] : d0[n0];
                    const int rA = ra + t * 16, rB = rA + 8;
                    *(float2*)&sAct[rA * 132 + cb] = make_float2(dd[0] + bt2.x, dd[1] + bt2.y);
                    *(float2*)&sAct[rB * 132 + cb] = make_float2(dd[2] + bt2.x, dd[3] + bt2.y);
                }
            }
            __syncthreads();

            // final contraction, split across 2 thread-halves (64 h each)
            {
                const int p  = tid & 127;
                const int hh = tid >> 7;           // 0 or 1
                u64 q0 = 0ull, q1 = 0ull, q2 = 0ull, q3 = 0ull, q4 = 0ull;
                const int hbase = hh * 64;
#pragma unroll 4
                for (int h = hbase; h < hbase + 64; h += 4) {
                    ulonglong2 a  = *(const ulonglong2*)&sAct[p * 132 + h];
                    ulonglong2 c0 = *(const ulonglong2*)&sm[SBC_F + 0 * 128 + h];
                    ulonglong2 c1 = *(const ulonglong2*)&sm[SBC_F + 1 * 128 + h];
                    ulonglong2 c2 = *(const ulonglong2*)&sm[SBC_F + 2 * 128 + h];
                    ulonglong2 c3 = *(const ulonglong2*)&sm[SBC_F + 3 * 128 + h];
                    ulonglong2 c4 = *(const ulonglong2*)&sm[SBC_F + 4 * 128 + h];
                    fma2(q0, a.x, c0.x); fma2(q0, a.y, c0.y);
                    fma2(q1, a.x, c1.x); fma2(q1, a.y, c1.y);
                    fma2(q2, a.x, c2.x); fma2(q2, a.y, c2.y);
                    fma2(q3, a.x, c3.x); fma2(q3, a.y, c3.y);
                    fma2(q4, a.x, c4.x); fma2(q4, a.y, c4.y);
                }
                float2 v0 = up2(q0), v1 = up2(q1), v2 = up2(q2), v3 = up2(q3), v4 = up2(q4);
                float s0 = v0.x + v0.y, s1 = v1.x + v1.y, s2 = v2.x + v2.y;
                float s3 = v3.x + v3.y, s4 = v4.x + v4.y;
                float* red = &sm[SW0_F];           // reuse dead W0 region
                if (hh == 1) {
                    red[p]       = s0; red[128 + p] = s1; red[256 + p] = s2;
                    red[384 + p] = s3; red[512 + p] = s4;
                }
                __syncthreads();
                if (hh == 0) {
                    const int pglob = p0 + p;
                    if (pglob < NPTS) {
                        float* dst = out + ((size_t)b * NPTS + pglob) * OUTD;
                        dst[0] = s0 + red[p];
                        dst[1] = s1 + red[128 + p];
                        dst[2] = s2 + red[256 + p];
                        dst[3] = s3 + red[384 + p];
                        dst[4] = s4 + red[512 + p];
                    }
                }
            }
        }
    }
}

// ---------------------------------------------------------------------------
extern "C" void kernel_launch(void* const* d_in, const int* in_sizes, int n_in,
                              void* d_out, int out_size)
{
    const float* coords = (const float*)d_in[0];
    const float* sdf    = (const float*)d_in[1];
    const float* params = (const float*)d_in[2];
    const float* Wb0    = (const float*)d_in[3];
    const float* bb0    = (const float*)d_in[4];
    const float* Wb     = (const float*)d_in[5];
    const float* bbv    = (const float*)d_in[6];
    const float* Wbf    = (const float*)d_in[7];
    const float* bbf    = (const float*)d_in[8];
    const float* ab     = (const float*)d_in[9];
    const float* wb     = (const float*)d_in[10];
    const float* Wt0    = (const float*)d_in[11];
    const float* bt0    = (const float*)d_in[12];
    const float* Wt     = (const float*)d_in[13];
    const float* bt     = (const float*)d_in[14];
    const float* Wtf    = (const float*)d_in[15];
    const float* btf    = (const float*)d_in[16];
    const float* at     = (const float*)d_in[17];
    const float* wt     = (const float*)d_in[18];
    float* out = (float*)d_out;

    cudaFuncSetAttribute(trunk_kernel, cudaFuncAttributeMaxDynamicSharedMemorySize, SMEM_BYTES);

    prep_kernel<<<80, 256>>>(Wt, Wtf, params, Wb0, bb0, Wb, bbv, Wbf, bbf, ab, wb);

    dim3 grid(NBLK, BB);
    trunk_kernel<<<grid, THR, SMEM_BYTES>>>(coords, sdf, Wt0, bt0, bt, btf,
                                            at, wt, out);
}